// round 1
// baseline (speedup 1.0000x reference)
#include <cuda_runtime.h>
#include <cuda_bf16.h>

#define BB 4
#define LEN 512
#define LEN1 512
#define DIM_IN 512
#define DIM_H 512
#define DIM_M 256
#define DIM_V 512

// Scratch (no allocations allowed): 2MB + 2MB + 4MB
__device__ float g_kx[BB * LEN * DIM_M];    // [b][l][m]
__device__ float g_qh[BB * LEN1 * DIM_M];   // [b][q][m]
__device__ float g_sc[BB * LEN1 * LEN];     // [b][q][l]  (transposed scores -> softmax over last dim)

__device__ __forceinline__ float tanh_fast(float x) {
    float y;
    asm("tanh.approx.f32 %0, %1;" : "=f"(y) : "f"(x));
    return y;
}

// ---------------------------------------------------------------------------
// Projections: C[r][m] = sum_k A[r][k] * W[m][k] (+ bias[m])
// R=2048 rows, K=512, M=256. z=0: keys@Wx -> g_kx ; z=1: query@Wh + bh -> g_qh
// 64x64 tile, 16x16 threads, 4x4 microtile.
// ---------------------------------------------------------------------------
__global__ __launch_bounds__(256) void proj_kernel(
    const float* __restrict__ A0, const float* __restrict__ A1,
    const float* __restrict__ W0, const float* __restrict__ W1,
    const float* __restrict__ bias1)
{
    const int K = 512, M = DIM_M;
    const float* A; const float* W; float* C; const float* bias;
    if (blockIdx.z == 0) { A = A0; W = W0; C = g_kx; bias = nullptr; }
    else                 { A = A1; W = W1; C = g_qh; bias = bias1; }

    __shared__ float As[16][64];   // [kk][r]
    __shared__ float Ws[16][64];   // [kk][m]

    int tid = threadIdx.x;
    int tx = tid & 15, ty = tid >> 4;
    int rb = blockIdx.y * 64;
    int mb = blockIdx.x * 64;
    int lr = tid >> 2;            // 0..63
    int lk = (tid & 3) << 2;      // 0,4,8,12

    float acc[4][4] = {};

    for (int k0 = 0; k0 < K; k0 += 16) {
        float4 a4 = *(const float4*)&A[(rb + lr) * K + k0 + lk];
        float4 w4 = *(const float4*)&W[(mb + lr) * K + k0 + lk];
        __syncthreads();
        As[lk + 0][lr] = a4.x; As[lk + 1][lr] = a4.y;
        As[lk + 2][lr] = a4.z; As[lk + 3][lr] = a4.w;
        Ws[lk + 0][lr] = w4.x; Ws[lk + 1][lr] = w4.y;
        Ws[lk + 2][lr] = w4.z; Ws[lk + 3][lr] = w4.w;
        __syncthreads();
        #pragma unroll
        for (int kk = 0; kk < 16; kk++) {
            float4 av = *(const float4*)&As[kk][ty << 2];
            float4 wv = *(const float4*)&Ws[kk][tx << 2];
            acc[0][0] += av.x * wv.x; acc[0][1] += av.x * wv.y;
            acc[0][2] += av.x * wv.z; acc[0][3] += av.x * wv.w;
            acc[1][0] += av.y * wv.x; acc[1][1] += av.y * wv.y;
            acc[1][2] += av.y * wv.z; acc[1][3] += av.y * wv.w;
            acc[2][0] += av.z * wv.x; acc[2][1] += av.z * wv.y;
            acc[2][2] += av.z * wv.z; acc[2][3] += av.z * wv.w;
            acc[3][0] += av.w * wv.x; acc[3][1] += av.w * wv.y;
            acc[3][2] += av.w * wv.z; acc[3][3] += av.w * wv.w;
        }
    }

    #pragma unroll
    for (int i = 0; i < 4; i++) {
        int r = rb + (ty << 2) + i;
        #pragma unroll
        for (int j = 0; j < 4; j++) {
            int m = mb + (tx << 2) + j;
            float v = acc[i][j];
            if (bias) v += bias[m];
            C[r * M + m] = v;
        }
    }
}

// ---------------------------------------------------------------------------
// Scores: sc[b][q][l] = sum_m w[m] * tanh(kx[b][l][m] + qh[b][q][m])
// 32(l) x 32(q) tile per block, 16x16 threads, 2x2 microtile.
// DIM_M processed in 2 chunks of 128 to keep static smem < 48KB.
// Shared layout [m][l] with pad 34 -> conflict-free float2 LDS in main loop.
// ---------------------------------------------------------------------------
__global__ __launch_bounds__(256) void score_kernel(const float* __restrict__ w)
{
    __shared__ float kxs[128][34];
    __shared__ float qhs[128][34];
    __shared__ float w_s[DIM_M];

    int tid = threadIdx.x;
    int tx = tid & 15, ty = tid >> 4;
    int lb = blockIdx.x * 32;
    int qb = blockIdx.y * 32;
    int b  = blockIdx.z;

    if (tid < DIM_M) w_s[tid] = w[tid];

    const float* kxp = g_kx + (b * LEN  + lb) * DIM_M;
    const float* qhp = g_qh + (b * LEN1 + qb) * DIM_M;

    float acc00 = 0.f, acc01 = 0.f, acc10 = 0.f, acc11 = 0.f;

    int mloc  = tid & 127;   // local m index for loads
    int lhalf = tid >> 7;    // 0 or 1: which 16 rows this thread loads

    for (int h = 0; h < 2; h++) {
        __syncthreads();
        int mg = h * 128 + mloc;
        #pragma unroll
        for (int i = 0; i < 16; i++) {
            int row = lhalf * 16 + i;
            kxs[mloc][row] = kxp[row * DIM_M + mg];
            qhs[mloc][row] = qhp[row * DIM_M + mg];
        }
        __syncthreads();

        #pragma unroll 8
        for (int mm = 0; mm < 128; mm++) {
            float  wm = w_s[h * 128 + mm];
            float2 qa = *(const float2*)&qhs[mm][ty * 2];
            float2 kb = *(const float2*)&kxs[mm][tx * 2];
            acc00 += wm * tanh_fast(qa.x + kb.x);
            acc01 += wm * tanh_fast(qa.x + kb.y);
            acc10 += wm * tanh_fast(qa.y + kb.x);
            acc11 += wm * tanh_fast(qa.y + kb.y);
        }
    }

    float* o = g_sc + (size_t)(b * LEN1 + qb + ty * 2) * LEN + lb + tx * 2;
    o[0]       = acc00; o[1]       = acc01;
    o[LEN]     = acc10; o[LEN + 1] = acc11;
}

// ---------------------------------------------------------------------------
// Softmax over last dim of g_sc (rows of 512). One block per row.
// ---------------------------------------------------------------------------
__global__ __launch_bounds__(256) void softmax_kernel()
{
    __shared__ float red[256];
    int row = blockIdx.x;               // 0..2047
    float* p = g_sc + (size_t)row * LEN;
    int t = threadIdx.x;

    float2 v = *(float2*)&p[t * 2];
    red[t] = fmaxf(v.x, v.y);
    __syncthreads();
    #pragma unroll
    for (int s = 128; s > 0; s >>= 1) {
        if (t < s) red[t] = fmaxf(red[t], red[t + s]);
        __syncthreads();
    }
    float rowmax = red[0];
    __syncthreads();

    float e0 = __expf(v.x - rowmax);
    float e1 = __expf(v.y - rowmax);
    red[t] = e0 + e1;
    __syncthreads();
    #pragma unroll
    for (int s = 128; s > 0; s >>= 1) {
        if (t < s) red[t] += red[t + s];
        __syncthreads();
    }
    float inv = 1.0f / red[0];

    float2 o; o.x = e0 * inv; o.y = e1 * inv;
    *(float2*)&p[t * 2] = o;
}

// ---------------------------------------------------------------------------
// Output GEMM: out[b][q][v] = sum_l e[b][q][l] * values[b][l][v]
// Batched 512x512x512 NN GEMM. 64x64 tile, 16x16 threads, 4x4 microtile.
// ---------------------------------------------------------------------------
__global__ __launch_bounds__(256) void av_kernel(
    const float* __restrict__ values, float* __restrict__ out)
{
    int bz = blockIdx.z;
    const float* E = g_sc   + (size_t)bz * LEN1 * LEN;
    const float* V = values + (size_t)bz * LEN * DIM_V;
    float*       C = out    + (size_t)bz * LEN1 * DIM_V;

    __shared__ float Es[16][68];  // [l][r], pad 68 (272B = 17*16 -> float4-aligned)
    __shared__ float Vs[16][64];  // [l][v]

    int tid = threadIdx.x;
    int tx = tid & 15, ty = tid >> 4;
    int rb = blockIdx.y * 64;
    int vb = blockIdx.x * 64;
    int lr = tid >> 2;            // 0..63 (E row)
    int lk = (tid & 3) << 2;      // l offset 0,4,8,12
    int vl = tid >> 4;            // 0..15 (V row)
    int vo = (tid & 15) << 2;     // v offset

    float acc[4][4] = {};

    for (int l0 = 0; l0 < LEN; l0 += 16) {
        float4 e4 = *(const float4*)&E[(rb + lr) * LEN + l0 + lk];
        float4 v4 = *(const float4*)&V[(l0 + vl) * DIM_V + vb + vo];
        __syncthreads();
        Es[lk + 0][lr] = e4.x; Es[lk + 1][lr] = e4.y;
        Es[lk + 2][lr] = e4.z; Es[lk + 3][lr] = e4.w;
        *(float4*)&Vs[vl][vo] = v4;
        __syncthreads();
        #pragma unroll
        for (int kk = 0; kk < 16; kk++) {
            float4 ev = *(const float4*)&Es[kk][ty << 2];
            float4 vv = *(const float4*)&Vs[kk][tx << 2];
            acc[0][0] += ev.x * vv.x; acc[0][1] += ev.x * vv.y;
            acc[0][2] += ev.x * vv.z; acc[0][3] += ev.x * vv.w;
            acc[1][0] += ev.y * vv.x; acc[1][1] += ev.y * vv.y;
            acc[1][2] += ev.y * vv.z; acc[1][3] += ev.y * vv.w;
            acc[2][0] += ev.z * vv.x; acc[2][1] += ev.z * vv.y;
            acc[2][2] += ev.z * vv.z; acc[2][3] += ev.z * vv.w;
            acc[3][0] += ev.w * vv.x; acc[3][1] += ev.w * vv.y;
            acc[3][2] += ev.w * vv.z; acc[3][3] += ev.w * vv.w;
        }
    }

    #pragma unroll
    for (int i = 0; i < 4; i++) {
        int r = rb + (ty << 2) + i;
        #pragma unroll
        for (int j = 0; j < 4; j++) {
            C[r * DIM_V + vb + (tx << 2) + j] = acc[i][j];
        }
    }
}

// ---------------------------------------------------------------------------
// Launch. Inputs (metadata order): query, keys, values, Wx, Wh, bh, w.
// Output: [B, LEN1, DIM_V] fp32.
// ---------------------------------------------------------------------------
extern "C" void kernel_launch(void* const* d_in, const int* in_sizes, int n_in,
                              void* d_out, int out_size)
{
    const float* query  = (const float*)d_in[0];
    const float* keys   = (const float*)d_in[1];
    const float* values = (const float*)d_in[2];
    const float* Wx     = (const float*)d_in[3];
    const float* Wh     = (const float*)d_in[4];
    const float* bh     = (const float*)d_in[5];
    const float* w      = (const float*)d_in[6];
    float* out = (float*)d_out;

    // Projections: z=0 keys@Wx -> g_kx, z=1 query@Wh + bh -> g_qh
    proj_kernel<<<dim3(DIM_M / 64, (BB * LEN) / 64, 2), 256>>>(keys, query, Wx, Wh, bh);

    // Fused tanh-score kernel: g_sc[b][q][l]
    score_kernel<<<dim3(LEN / 32, LEN1 / 32, BB), 256>>>(w);

    // Softmax over key axis (rows of transposed scores)
    softmax_kernel<<<BB * LEN1, 256>>>();

    // out = e @ values (batched)
    av_kernel<<<dim3(DIM_V / 64, LEN1 / 64, BB), 256>>>(values, out);
}

// round 2
// speedup vs baseline: 1.1007x; 1.1007x over previous
#include <cuda_runtime.h>
#include <cuda_bf16.h>

#define BB 4
#define LEN 512
#define LEN1 512
#define DIM_IN 512
#define DIM_H 512
#define DIM_M 256
#define DIM_V 512

// Scratch (no allocations allowed)
__device__ float g_kx[BB * LEN * DIM_M];    // [b][l][m]
__device__ float g_qh[BB * LEN1 * DIM_M];   // [b][q][m]
__device__ float g_sc[BB * LEN1 * LEN];     // [b][q][l]  (transposed scores)

__device__ __forceinline__ float tanh_fast(float x) {
    float y;
    asm("tanh.approx.f32 %0, %1;" : "=f"(y) : "f"(x));
    return y;
}

// ---- packed f32x2 helpers (sm_100 double-rate fp32 FMA path) ----
__device__ __forceinline__ unsigned long long pack2(float a, float b) {
    unsigned long long r;
    asm("mov.b64 %0, {%1, %2};" : "=l"(r) : "f"(a), "f"(b));
    return r;
}
__device__ __forceinline__ unsigned long long fma2(unsigned long long a,
                                                   unsigned long long b,
                                                   unsigned long long c) {
    unsigned long long d;
    asm("fma.rn.f32x2 %0, %1, %2, %3;" : "=l"(d) : "l"(a), "l"(b), "l"(c));
    return d;
}
__device__ __forceinline__ float2 unpack2(unsigned long long v) {
    float2 f;
    asm("mov.b64 {%0, %1}, %2;" : "=f"(f.x), "=f"(f.y) : "l"(v));
    return f;
}

// ---------------------------------------------------------------------------
// Projections (NT GEMM): C[r][m] = sum_k A[r][k] * W[m][k] (+ bias[m])
// R=2048 rows, K=512, M=256. z=0: keys@Wx -> g_kx ; z=1: query@Wh + bh -> g_qh
// 64x64 tile, 256 threads, 4x4 microtile, double-buffered smem, f32x2 FMA.
// ---------------------------------------------------------------------------
__global__ __launch_bounds__(256) void proj_kernel(
    const float* __restrict__ A0, const float* __restrict__ A1,
    const float* __restrict__ W0, const float* __restrict__ W1,
    const float* __restrict__ bias1)
{
    const int K = 512, M = DIM_M;
    const float* A; const float* W; float* C; const float* bias;
    if (blockIdx.z == 0) { A = A0; W = W0; C = g_kx; bias = nullptr; }
    else                 { A = A1; W = W1; C = g_qh; bias = bias1; }

    __shared__ __align__(16) float As[2][16][68];   // [buf][kk][r]
    __shared__ __align__(16) float Ws[2][16][68];   // [buf][kk][m]

    int tid = threadIdx.x;
    int tx = tid & 15, ty = tid >> 4;
    int rb = blockIdx.y * 64;
    int mb = blockIdx.x * 64;
    int lr = tid >> 2;            // 0..63
    int lk = (tid & 3) << 2;      // 0,4,8,12

    const float* Ap = &A[(rb + lr) * K + lk];
    const float* Wp = &W[(mb + lr) * K + lk];

    unsigned long long acc[4][2] = {};  // [row i][col pair]

    float4 a4 = *(const float4*)Ap;
    float4 w4 = *(const float4*)Wp;
    As[0][lk + 0][lr] = a4.x; As[0][lk + 1][lr] = a4.y;
    As[0][lk + 2][lr] = a4.z; As[0][lk + 3][lr] = a4.w;
    Ws[0][lk + 0][lr] = w4.x; Ws[0][lk + 1][lr] = w4.y;
    Ws[0][lk + 2][lr] = w4.z; Ws[0][lk + 3][lr] = w4.w;
    __syncthreads();

    int buf = 0;
    for (int k0 = 16; ; k0 += 16) {
        bool more = (k0 < K);
        if (more) {
            a4 = *(const float4*)(Ap + k0);
            w4 = *(const float4*)(Wp + k0);
        }
        #pragma unroll
        for (int kk = 0; kk < 16; kk++) {
            float4 av = *(const float4*)&As[buf][kk][ty << 2];
            ulonglong2 wv = *(const ulonglong2*)&Ws[buf][kk][tx << 2];
            unsigned long long aa;
            aa = pack2(av.x, av.x);
            acc[0][0] = fma2(aa, wv.x, acc[0][0]);
            acc[0][1] = fma2(aa, wv.y, acc[0][1]);
            aa = pack2(av.y, av.y);
            acc[1][0] = fma2(aa, wv.x, acc[1][0]);
            acc[1][1] = fma2(aa, wv.y, acc[1][1]);
            aa = pack2(av.z, av.z);
            acc[2][0] = fma2(aa, wv.x, acc[2][0]);
            acc[2][1] = fma2(aa, wv.y, acc[2][1]);
            aa = pack2(av.w, av.w);
            acc[3][0] = fma2(aa, wv.x, acc[3][0]);
            acc[3][1] = fma2(aa, wv.y, acc[3][1]);
        }
        if (!more) break;
        int nb = buf ^ 1;
        As[nb][lk + 0][lr] = a4.x; As[nb][lk + 1][lr] = a4.y;
        As[nb][lk + 2][lr] = a4.z; As[nb][lk + 3][lr] = a4.w;
        Ws[nb][lk + 0][lr] = w4.x; Ws[nb][lk + 1][lr] = w4.y;
        Ws[nb][lk + 2][lr] = w4.z; Ws[nb][lk + 3][lr] = w4.w;
        __syncthreads();
        buf = nb;
    }

    #pragma unroll
    for (int i = 0; i < 4; i++) {
        int r = rb + (ty << 2) + i;
        int m = mb + (tx << 2);
        float2 p0 = unpack2(acc[i][0]);
        float2 p1 = unpack2(acc[i][1]);
        float4 o;
        o.x = p0.x; o.y = p0.y; o.z = p1.x; o.w = p1.y;
        if (bias) {
            o.x += bias[m + 0]; o.y += bias[m + 1];
            o.z += bias[m + 2]; o.w += bias[m + 3];
        }
        *(float4*)&C[r * M + m] = o;
    }
}

// ---------------------------------------------------------------------------
// Scores: sc[b][q][l] = sum_m w[m] * tanh(kx[b][l][m] + qh[b][q][m])
// (unchanged from passing round-1 kernel: MUFU-bound)
// ---------------------------------------------------------------------------
__global__ __launch_bounds__(256) void score_kernel(const float* __restrict__ w)
{
    __shared__ float kxs[128][34];
    __shared__ float qhs[128][34];
    __shared__ float w_s[DIM_M];

    int tid = threadIdx.x;
    int tx = tid & 15, ty = tid >> 4;
    int lb = blockIdx.x * 32;
    int qb = blockIdx.y * 32;
    int b  = blockIdx.z;

    if (tid < DIM_M) w_s[tid] = w[tid];

    const float* kxp = g_kx + (b * LEN  + lb) * DIM_M;
    const float* qhp = g_qh + (b * LEN1 + qb) * DIM_M;

    float acc00 = 0.f, acc01 = 0.f, acc10 = 0.f, acc11 = 0.f;

    int mloc  = tid & 127;
    int lhalf = tid >> 7;

    for (int h = 0; h < 2; h++) {
        __syncthreads();
        int mg = h * 128 + mloc;
        #pragma unroll
        for (int i = 0; i < 16; i++) {
            int row = lhalf * 16 + i;
            kxs[mloc][row] = kxp[row * DIM_M + mg];
            qhs[mloc][row] = qhp[row * DIM_M + mg];
        }
        __syncthreads();

        #pragma unroll 8
        for (int mm = 0; mm < 128; mm++) {
            float  wm = w_s[h * 128 + mm];
            float2 qa = *(const float2*)&qhs[mm][ty * 2];
            float2 kb = *(const float2*)&kxs[mm][tx * 2];
            acc00 += wm * tanh_fast(qa.x + kb.x);
            acc01 += wm * tanh_fast(qa.x + kb.y);
            acc10 += wm * tanh_fast(qa.y + kb.x);
            acc11 += wm * tanh_fast(qa.y + kb.y);
        }
    }

    float* o = g_sc + (size_t)(b * LEN1 + qb + ty * 2) * LEN + lb + tx * 2;
    o[0]       = acc00; o[1]       = acc01;
    o[LEN]     = acc10; o[LEN + 1] = acc11;
}

// ---------------------------------------------------------------------------
// Softmax over last dim of g_sc (rows of 512). One block per row.
// ---------------------------------------------------------------------------
__global__ __launch_bounds__(256) void softmax_kernel()
{
    __shared__ float red[256];
    int row = blockIdx.x;
    float* p = g_sc + (size_t)row * LEN;
    int t = threadIdx.x;

    float2 v = *(float2*)&p[t * 2];
    red[t] = fmaxf(v.x, v.y);
    __syncthreads();
    #pragma unroll
    for (int s = 128; s > 0; s >>= 1) {
        if (t < s) red[t] = fmaxf(red[t], red[t + s]);
        __syncthreads();
    }
    float rowmax = red[0];
    __syncthreads();

    float e0 = __expf(v.x - rowmax);
    float e1 = __expf(v.y - rowmax);
    red[t] = e0 + e1;
    __syncthreads();
    #pragma unroll
    for (int s = 128; s > 0; s >>= 1) {
        if (t < s) red[t] += red[t + s];
        __syncthreads();
    }
    float inv = 1.0f / red[0];

    float2 o; o.x = e0 * inv; o.y = e1 * inv;
    *(float2*)&p[t * 2] = o;
}

// ---------------------------------------------------------------------------
// Output GEMM (NN): out[b][q][v] = sum_l e[b][q][l] * values[b][l][v]
// Batched 512x512x512. 64x64 tile, 256 threads, 4x4 microtile,
// double-buffered smem, f32x2 FMA.
// ---------------------------------------------------------------------------
__global__ __launch_bounds__(256) void av_kernel(
    const float* __restrict__ values, float* __restrict__ out)
{
    int bz = blockIdx.z;
    const float* E = g_sc   + (size_t)bz * LEN1 * LEN;
    const float* V = values + (size_t)bz * LEN * DIM_V;
    float*       C = out    + (size_t)bz * LEN1 * DIM_V;

    __shared__ __align__(16) float Es[2][16][68];  // [buf][l][r]
    __shared__ __align__(16) float Vs[2][16][68];  // [buf][l][v]

    int tid = threadIdx.x;
    int tx = tid & 15, ty = tid >> 4;
    int rb = blockIdx.y * 64;
    int vb = blockIdx.x * 64;
    int lr = tid >> 2;            // 0..63 (E row)
    int lk = (tid & 3) << 2;      // l offset 0,4,8,12
    int vl = tid >> 4;            // 0..15 (V row)
    int vo = (tid & 15) << 2;     // v offset

    const float* Ep = &E[(rb + lr) * LEN + lk];
    const float* Vp = &V[vl * DIM_V + vb + vo];

    unsigned long long acc[4][2] = {};

    float4 e4 = *(const float4*)Ep;
    float4 v4 = *(const float4*)Vp;
    Es[0][lk + 0][lr] = e4.x; Es[0][lk + 1][lr] = e4.y;
    Es[0][lk + 2][lr] = e4.z; Es[0][lk + 3][lr] = e4.w;
    *(float4*)&Vs[0][vl][vo] = v4;
    __syncthreads();

    int buf = 0;
    for (int l0 = 16; ; l0 += 16) {
        bool more = (l0 < LEN);
        if (more) {
            e4 = *(const float4*)(Ep + l0);
            v4 = *(const float4*)(Vp + (size_t)l0 * DIM_V);
        }
        #pragma unroll
        for (int kk = 0; kk < 16; kk++) {
            float4 ev = *(const float4*)&Es[buf][kk][ty << 2];
            ulonglong2 vv = *(const ulonglong2*)&Vs[buf][kk][tx << 2];
            unsigned long long aa;
            aa = pack2(ev.x, ev.x);
            acc[0][0] = fma2(aa, vv.x, acc[0][0]);
            acc[0][1] = fma2(aa, vv.y, acc[0][1]);
            aa = pack2(ev.y, ev.y);
            acc[1][0] = fma2(aa, vv.x, acc[1][0]);
            acc[1][1] = fma2(aa, vv.y, acc[1][1]);
            aa = pack2(ev.z, ev.z);
            acc[2][0] = fma2(aa, vv.x, acc[2][0]);
            acc[2][1] = fma2(aa, vv.y, acc[2][1]);
            aa = pack2(ev.w, ev.w);
            acc[3][0] = fma2(aa, vv.x, acc[3][0]);
            acc[3][1] = fma2(aa, vv.y, acc[3][1]);
        }
        if (!more) break;
        int nb = buf ^ 1;
        Es[nb][lk + 0][lr] = e4.x; Es[nb][lk + 1][lr] = e4.y;
        Es[nb][lk + 2][lr] = e4.z; Es[nb][lk + 3][lr] = e4.w;
        *(float4*)&Vs[nb][vl][vo] = v4;
        __syncthreads();
        buf = nb;
    }

    #pragma unroll
    for (int i = 0; i < 4; i++) {
        int r = rb + (ty << 2) + i;
        float2 p0 = unpack2(acc[i][0]);
        float2 p1 = unpack2(acc[i][1]);
        float4 o;
        o.x = p0.x; o.y = p0.y; o.z = p1.x; o.w = p1.y;
        *(float4*)&C[r * DIM_V + vb + (tx << 2)] = o;
    }
}

// ---------------------------------------------------------------------------
// Launch. Inputs (metadata order): query, keys, values, Wx, Wh, bh, w.
// Output: [B, LEN1, DIM_V] fp32.
// ---------------------------------------------------------------------------
extern "C" void kernel_launch(void* const* d_in, const int* in_sizes, int n_in,
                              void* d_out, int out_size)
{
    const float* query  = (const float*)d_in[0];
    const float* keys   = (const float*)d_in[1];
    const float* values = (const float*)d_in[2];
    const float* Wx     = (const float*)d_in[3];
    const float* Wh     = (const float*)d_in[4];
    const float* bh     = (const float*)d_in[5];
    const float* w      = (const float*)d_in[6];
    float* out = (float*)d_out;

    proj_kernel<<<dim3(DIM_M / 64, (BB * LEN) / 64, 2), 256>>>(keys, query, Wx, Wh, bh);
    score_kernel<<<dim3(LEN / 32, LEN1 / 32, BB), 256>>>(w);
    softmax_kernel<<<BB * LEN1, 256>>>();
    av_kernel<<<dim3(DIM_V / 64, LEN1 / 64, BB), 256>>>(values, out);
}

// round 3
// speedup vs baseline: 1.3660x; 1.2410x over previous
#include <cuda_runtime.h>
#include <cuda_bf16.h>

#define BB 4
#define LEN 512
#define LEN1 512
#define DIM_IN 512
#define DIM_H 512
#define DIM_M 256
#define DIM_V 512

#define LDK 20   // smem k-stride (16 k + 4 pad) -> conflict-free tf32 frag loads
#define LDN 72   // smem n-stride (64 n + 8 pad) for NN B tiles

// Scratch
__device__ float g_kx[BB * LEN * DIM_M];    // [b][l][m]
__device__ float g_qh[BB * LEN1 * DIM_M];   // [b][q][m]
__device__ float g_sc[BB * LEN1 * LEN];     // [b][q][l]

__device__ __forceinline__ float tanh_fast(float x) {
    float y;
    asm("tanh.approx.f32 %0, %1;" : "=f"(y) : "f"(x));
    return y;
}

// ---- tf32 helpers ----
__device__ __forceinline__ unsigned f2tf(float x) {
    unsigned u;
    asm("cvt.rna.tf32.f32 %0, %1;" : "=r"(u) : "f"(x));
    return u;
}
__device__ __forceinline__ uint4 cvt4(float4 v) {
    uint4 u;
    u.x = f2tf(v.x); u.y = f2tf(v.y); u.z = f2tf(v.z); u.w = f2tf(v.w);
    return u;
}
__device__ __forceinline__ void mma_tf32(float* d, const unsigned* a, const unsigned* b) {
    asm volatile(
        "mma.sync.aligned.m16n8k8.row.col.f32.tf32.tf32.f32 "
        "{%0,%1,%2,%3}, {%4,%5,%6,%7}, {%8,%9}, {%0,%1,%2,%3};"
        : "+f"(d[0]), "+f"(d[1]), "+f"(d[2]), "+f"(d[3])
        : "r"(a[0]), "r"(a[1]), "r"(a[2]), "r"(a[3]), "r"(b[0]), "r"(b[1]));
}

// ---------------------------------------------------------------------------
// proj (NT, tensor core): C[r][m] = sum_k A[r][k] * W[m][k] (+ bias)
// R=2048, N=256, K=512. Block tile 128x64, 8 warps (4m x 2n), warp 32x32.
// z=0: keys@Wx -> g_kx ; z=1: query@Wh + bh -> g_qh. Grid = 64*2 = 128 blocks.
// ---------------------------------------------------------------------------
__global__ __launch_bounds__(256) void proj_tc(
    const float* __restrict__ A0, const float* __restrict__ A1,
    const float* __restrict__ W0, const float* __restrict__ W1,
    const float* __restrict__ bias1)
{
    const float* A; const float* W; float* C; const float* bias;
    if (blockIdx.z == 0) { A = A0; W = W0; C = g_kx; bias = nullptr; }
    else                 { A = A1; W = W1; C = g_qh; bias = bias1; }

    __shared__ unsigned As[2][128 * LDK];
    __shared__ unsigned Bs[2][64 * LDK];

    int tid = threadIdx.x;
    int lane = tid & 31;
    int wid = tid >> 5;
    int warp_m = (wid >> 1) * 32;
    int warp_n = (wid & 1) * 32;
    int gid = lane >> 2;       // 0..7
    int tig = lane & 3;        // 0..3

    int rb = blockIdx.y * 128;
    int nb = blockIdx.x * 64;

    int lr = tid >> 2;         // 0..63
    int kq = (tid & 3) * 4;    // 0,4,8,12

    const float* Ap0 = A + (size_t)(rb + lr) * 512 + kq;
    const float* Ap1 = A + (size_t)(rb + lr + 64) * 512 + kq;
    const float* Wp  = W + (size_t)(nb + lr) * 512 + kq;

    float acc[2][4][4] = {};

    float4 a0v = *(const float4*)Ap0;
    float4 a1v = *(const float4*)Ap1;
    float4 wv  = *(const float4*)Wp;
    *(uint4*)&As[0][lr * LDK + kq]        = cvt4(a0v);
    *(uint4*)&As[0][(lr + 64) * LDK + kq] = cvt4(a1v);
    *(uint4*)&Bs[0][lr * LDK + kq]        = cvt4(wv);
    __syncthreads();

    int buf = 0;
    for (int k0 = 16; ; k0 += 16) {
        bool more = (k0 < 512);
        if (more) {
            a0v = *(const float4*)(Ap0 + k0);
            a1v = *(const float4*)(Ap1 + k0);
            wv  = *(const float4*)(Wp  + k0);
        }
        #pragma unroll
        for (int ks = 0; ks < 16; ks += 8) {
            unsigned af[2][4], bf[4][2];
            #pragma unroll
            for (int mm = 0; mm < 2; mm++) {
                const unsigned* p = &As[buf][(warp_m + mm * 16 + gid) * LDK + ks + tig];
                af[mm][0] = p[0];
                af[mm][1] = p[8 * LDK];
                af[mm][2] = p[4];
                af[mm][3] = p[8 * LDK + 4];
            }
            #pragma unroll
            for (int nn = 0; nn < 4; nn++) {
                const unsigned* p = &Bs[buf][(warp_n + nn * 8 + gid) * LDK + ks + tig];
                bf[nn][0] = p[0];
                bf[nn][1] = p[4];
            }
            #pragma unroll
            for (int mm = 0; mm < 2; mm++)
                #pragma unroll
                for (int nn = 0; nn < 4; nn++)
                    mma_tf32(acc[mm][nn], af[mm], bf[nn]);
        }
        if (!more) break;
        int nbuf = buf ^ 1;
        *(uint4*)&As[nbuf][lr * LDK + kq]        = cvt4(a0v);
        *(uint4*)&As[nbuf][(lr + 64) * LDK + kq] = cvt4(a1v);
        *(uint4*)&Bs[nbuf][lr * LDK + kq]        = cvt4(wv);
        __syncthreads();
        buf = nbuf;
    }

    #pragma unroll
    for (int mm = 0; mm < 2; mm++) {
        int r0 = rb + warp_m + mm * 16 + gid;
        #pragma unroll
        for (int nn = 0; nn < 4; nn++) {
            int c = nb + warp_n + nn * 8 + 2 * tig;
            float2 v0 = make_float2(acc[mm][nn][0], acc[mm][nn][1]);
            float2 v1 = make_float2(acc[mm][nn][2], acc[mm][nn][3]);
            if (bias) {
                float2 bb = *(const float2*)&bias[c];
                v0.x += bb.x; v0.y += bb.y;
                v1.x += bb.x; v1.y += bb.y;
            }
            *(float2*)&C[(size_t)r0 * DIM_M + c]       = v0;
            *(float2*)&C[(size_t)(r0 + 8) * DIM_M + c] = v1;
        }
    }
}

// ---------------------------------------------------------------------------
// Scores: sc[b][q][l] = sum_m w[m] * tanh(kx[b][l][m] + qh[b][q][m])
// (unchanged: MUFU-bound, near floor)
// ---------------------------------------------------------------------------
__global__ __launch_bounds__(256) void score_kernel(const float* __restrict__ w)
{
    __shared__ float kxs[128][34];
    __shared__ float qhs[128][34];
    __shared__ float w_s[DIM_M];

    int tid = threadIdx.x;
    int tx = tid & 15, ty = tid >> 4;
    int lb = blockIdx.x * 32;
    int qb = blockIdx.y * 32;
    int b  = blockIdx.z;

    if (tid < DIM_M) w_s[tid] = w[tid];

    const float* kxp = g_kx + (b * LEN  + lb) * DIM_M;
    const float* qhp = g_qh + (b * LEN1 + qb) * DIM_M;

    float acc00 = 0.f, acc01 = 0.f, acc10 = 0.f, acc11 = 0.f;

    int mloc  = tid & 127;
    int lhalf = tid >> 7;

    for (int h = 0; h < 2; h++) {
        __syncthreads();
        int mg = h * 128 + mloc;
        #pragma unroll
        for (int i = 0; i < 16; i++) {
            int row = lhalf * 16 + i;
            kxs[mloc][row] = kxp[row * DIM_M + mg];
            qhs[mloc][row] = qhp[row * DIM_M + mg];
        }
        __syncthreads();

        #pragma unroll 8
        for (int mm = 0; mm < 128; mm++) {
            float  wm = w_s[h * 128 + mm];
            float2 qa = *(const float2*)&qhs[mm][ty * 2];
            float2 kb = *(const float2*)&kxs[mm][tx * 2];
            acc00 += wm * tanh_fast(qa.x + kb.x);
            acc01 += wm * tanh_fast(qa.x + kb.y);
            acc10 += wm * tanh_fast(qa.y + kb.x);
            acc11 += wm * tanh_fast(qa.y + kb.y);
        }
    }

    float* o = g_sc + (size_t)(b * LEN1 + qb + ty * 2) * LEN + lb + tx * 2;
    o[0]       = acc00; o[1]       = acc01;
    o[LEN]     = acc10; o[LEN + 1] = acc11;
}

// ---------------------------------------------------------------------------
// Softmax over last dim of g_sc (rows of 512). One block per row.
// ---------------------------------------------------------------------------
__global__ __launch_bounds__(256) void softmax_kernel()
{
    __shared__ float red[256];
    int row = blockIdx.x;
    float* p = g_sc + (size_t)row * LEN;
    int t = threadIdx.x;

    float2 v = *(float2*)&p[t * 2];
    red[t] = fmaxf(v.x, v.y);
    __syncthreads();
    #pragma unroll
    for (int s = 128; s > 0; s >>= 1) {
        if (t < s) red[t] = fmaxf(red[t], red[t + s]);
        __syncthreads();
    }
    float rowmax = red[0];
    __syncthreads();

    float e0 = __expf(v.x - rowmax);
    float e1 = __expf(v.y - rowmax);
    red[t] = e0 + e1;
    __syncthreads();
    #pragma unroll
    for (int s = 128; s > 0; s >>= 1) {
        if (t < s) red[t] += red[t + s];
        __syncthreads();
    }
    float inv = 1.0f / red[0];

    float2 o; o.x = e0 * inv; o.y = e1 * inv;
    *(float2*)&p[t * 2] = o;
}

// ---------------------------------------------------------------------------
// av (NN, tensor core): out[b][q][v] = sum_l e[b][q][l] * values[b][l][v]
// Batched 512x512x512. Block 128(q) x 64(v), 8 warps, warp 32x32.
// Grid = 32*4 = 128 blocks.
// ---------------------------------------------------------------------------
__global__ __launch_bounds__(256) void av_tc(
    const float* __restrict__ values, float* __restrict__ out)
{
    int bz = blockIdx.z;
    const float* E = g_sc   + (size_t)bz * LEN1 * LEN;
    const float* V = values + (size_t)bz * LEN * DIM_V;
    float*       C = out    + (size_t)bz * LEN1 * DIM_V;

    __shared__ unsigned Es[2][128 * LDK];
    __shared__ unsigned Vs[2][16 * LDN];

    int tid = threadIdx.x;
    int lane = tid & 31;
    int wid = tid >> 5;
    int warp_m = (wid >> 1) * 32;
    int warp_n = (wid & 1) * 32;
    int gid = lane >> 2;
    int tig = lane & 3;

    int rb = blockIdx.y * 128;   // q
    int nb = blockIdx.x * 64;    // v

    int lr = tid >> 2;           // 0..63
    int kq = (tid & 3) * 4;      // 0,4,8,12
    int vl = tid >> 4;           // 0..15 (V k-row)
    int vn = (tid & 15) * 4;     // v offset

    const float* Ep0 = E + (size_t)(rb + lr) * LEN + kq;
    const float* Ep1 = E + (size_t)(rb + lr + 64) * LEN + kq;
    const float* Vp  = V + (size_t)vl * DIM_V + nb + vn;

    float acc[2][4][4] = {};

    float4 e0v = *(const float4*)Ep0;
    float4 e1v = *(const float4*)Ep1;
    float4 vv  = *(const float4*)Vp;
    *(uint4*)&Es[0][lr * LDK + kq]        = cvt4(e0v);
    *(uint4*)&Es[0][(lr + 64) * LDK + kq] = cvt4(e1v);
    *(uint4*)&Vs[0][vl * LDN + vn]        = cvt4(vv);
    __syncthreads();

    int buf = 0;
    for (int k0 = 16; ; k0 += 16) {
        bool more = (k0 < LEN);
        if (more) {
            e0v = *(const float4*)(Ep0 + k0);
            e1v = *(const float4*)(Ep1 + k0);
            vv  = *(const float4*)(Vp + (size_t)k0 * DIM_V);
        }
        #pragma unroll
        for (int ks = 0; ks < 16; ks += 8) {
            unsigned af[2][4], bf[4][2];
            #pragma unroll
            for (int mm = 0; mm < 2; mm++) {
                const unsigned* p = &Es[buf][(warp_m + mm * 16 + gid) * LDK + ks + tig];
                af[mm][0] = p[0];
                af[mm][1] = p[8 * LDK];
                af[mm][2] = p[4];
                af[mm][3] = p[8 * LDK + 4];
            }
            #pragma unroll
            for (int nn = 0; nn < 4; nn++) {
                const unsigned* p = &Vs[buf][(ks + tig) * LDN + warp_n + nn * 8 + gid];
                bf[nn][0] = p[0];
                bf[nn][1] = p[4 * LDN];
            }
            #pragma unroll
            for (int mm = 0; mm < 2; mm++)
                #pragma unroll
                for (int nn = 0; nn < 4; nn++)
                    mma_tf32(acc[mm][nn], af[mm], bf[nn]);
        }
        if (!more) break;
        int nbuf = buf ^ 1;
        *(uint4*)&Es[nbuf][lr * LDK + kq]        = cvt4(e0v);
        *(uint4*)&Es[nbuf][(lr + 64) * LDK + kq] = cvt4(e1v);
        *(uint4*)&Vs[nbuf][vl * LDN + vn]        = cvt4(vv);
        __syncthreads();
        buf = nbuf;
    }

    #pragma unroll
    for (int mm = 0; mm < 2; mm++) {
        int r0 = rb + warp_m + mm * 16 + gid;
        #pragma unroll
        for (int nn = 0; nn < 4; nn++) {
            int c = nb + warp_n + nn * 8 + 2 * tig;
            *(float2*)&C[(size_t)r0 * DIM_V + c] =
                make_float2(acc[mm][nn][0], acc[mm][nn][1]);
            *(float2*)&C[(size_t)(r0 + 8) * DIM_V + c] =
                make_float2(acc[mm][nn][2], acc[mm][nn][3]);
        }
    }
}

// ---------------------------------------------------------------------------
// Launch. Inputs: query, keys, values, Wx, Wh, bh, w. Output [B, LEN1, DIM_V].
// ---------------------------------------------------------------------------
extern "C" void kernel_launch(void* const* d_in, const int* in_sizes, int n_in,
                              void* d_out, int out_size)
{
    const float* query  = (const float*)d_in[0];
    const float* keys   = (const float*)d_in[1];
    const float* values = (const float*)d_in[2];
    const float* Wx     = (const float*)d_in[3];
    const float* Wh     = (const float*)d_in[4];
    const float* bh     = (const float*)d_in[5];
    const float* w      = (const float*)d_in[6];
    float* out = (float*)d_out;

    proj_tc<<<dim3(DIM_M / 64, (BB * LEN) / 128, 2), 256>>>(keys, query, Wx, Wh, bh);
    score_kernel<<<dim3(LEN / 32, LEN1 / 32, BB), 256>>>(w);
    softmax_kernel<<<BB * LEN1, 256>>>();
    av_tc<<<dim3(DIM_V / 64, LEN1 / 128, BB), 256>>>(values, out);
}

// round 4
// speedup vs baseline: 1.4940x; 1.0937x over previous
#include <cuda_runtime.h>
#include <cuda_bf16.h>
#include <cstdint>

#define BB 4
#define LEN 512
#define LEN1 512
#define DIM_IN 512
#define DIM_H 512
#define DIM_M 256
#define DIM_V 512

#define LDK 20   // smem k-stride (16 k + 4 pad floats); 80B = 16B-aligned
#define LDN 72   // smem n-stride (64 n + 8 pad floats); 288B = 16B-aligned

// Scratch
__device__ __align__(16) float g_kx[BB * LEN * DIM_M];    // [b][l][m]
__device__ __align__(16) float g_qh[BB * LEN1 * DIM_M];   // [b][q][m]
__device__ __align__(16) float g_sc[BB * LEN1 * LEN];     // [b][q][l]

__device__ __forceinline__ float tanh_fast(float x) {
    float y;
    asm("tanh.approx.f32 %0, %1;" : "=f"(y) : "f"(x));
    return y;
}

// ---- tf32 / mma helpers ----
__device__ __forceinline__ unsigned f2tf(float x) {
    unsigned u;
    asm("cvt.rna.tf32.f32 %0, %1;" : "=r"(u) : "f"(x));
    return u;
}
__device__ __forceinline__ void mma_tf32(float* d, const unsigned* a, const unsigned* b) {
    asm volatile(
        "mma.sync.aligned.m16n8k8.row.col.f32.tf32.tf32.f32 "
        "{%0,%1,%2,%3}, {%4,%5,%6,%7}, {%8,%9}, {%0,%1,%2,%3};"
        : "+f"(d[0]), "+f"(d[1]), "+f"(d[2]), "+f"(d[3])
        : "r"(a[0]), "r"(a[1]), "r"(a[2]), "r"(a[3]), "r"(b[0]), "r"(b[1]));
}

// ---- cp.async helpers ----
__device__ __forceinline__ void cp16(uint32_t smem_dst, const void* gmem_src) {
    asm volatile("cp.async.cg.shared.global [%0], [%1], 16;"
                 :: "r"(smem_dst), "l"(gmem_src));
}
#define CP_COMMIT() asm volatile("cp.async.commit_group;")
#define CP_WAIT2()  asm volatile("cp.async.wait_group 2;" ::: "memory")

// ---------------------------------------------------------------------------
// proj (NT, tensor core, 4-stage cp.async):
// C[r][m] = sum_k A[r][k] * W[m][k] (+ bias). R=2048, N=256, K=512.
// Block tile 64x64, 128 threads, 4 warps (2x2), warp 32x32.
// z=0: keys@Wx -> g_kx ; z=1: query@Wh + bh -> g_qh. Grid = 4*32*2 = 256.
// ---------------------------------------------------------------------------
__global__ __launch_bounds__(128) void proj_tc(
    const float* __restrict__ A0, const float* __restrict__ A1,
    const float* __restrict__ W0, const float* __restrict__ W1,
    const float* __restrict__ bias1)
{
    const float* A; const float* W; float* C; const float* bias;
    if (blockIdx.z == 0) { A = A0; W = W0; C = g_kx; bias = nullptr; }
    else                 { A = A1; W = W1; C = g_qh; bias = bias1; }

    __shared__ __align__(16) float As[4][64 * LDK];
    __shared__ __align__(16) float Ws[4][64 * LDK];

    int tid  = threadIdx.x;
    int lane = tid & 31;
    int wid  = tid >> 5;
    int warp_m = (wid & 1) * 32;
    int warp_n = (wid >> 1) * 32;
    int gid = lane >> 2;       // 0..7
    int tig = lane & 3;        // 0..3

    int rb = blockIdx.y * 64;
    int nb = blockIdx.x * 64;

    // cp.async mapping: 64 rows x 16k per tile; thread -> (row = tid>>1, ku = (tid&1)*8)
    int crow = tid >> 1;
    int cku  = (tid & 1) * 8;
    const float* Agp = A + (size_t)(rb + crow) * 512 + cku;
    const float* Wgp = W + (size_t)(nb + crow) * 512 + cku;
    uint32_t sA = (uint32_t)__cvta_generic_to_shared(&As[0][0]) + (crow * LDK + cku) * 4;
    uint32_t sW = (uint32_t)__cvta_generic_to_shared(&Ws[0][0]) + (crow * LDK + cku) * 4;
    const uint32_t stageB = 64 * LDK * 4;

    float acc[2][4][4] = {};

    #pragma unroll
    for (int s = 0; s < 3; s++) {
        cp16(sA + s * stageB,      Agp + s * 16);
        cp16(sA + s * stageB + 16, Agp + s * 16 + 4);
        cp16(sW + s * stageB,      Wgp + s * 16);
        cp16(sW + s * stageB + 16, Wgp + s * 16 + 4);
        CP_COMMIT();
    }

    for (int i = 0; i < 32; i++) {
        CP_WAIT2();
        __syncthreads();
        int ls = i + 3;
        if (ls < 32) {
            uint32_t off = (uint32_t)(ls & 3) * stageB;
            cp16(sA + off,      Agp + ls * 16);
            cp16(sA + off + 16, Agp + ls * 16 + 4);
            cp16(sW + off,      Wgp + ls * 16);
            cp16(sW + off + 16, Wgp + ls * 16 + 4);
        }
        CP_COMMIT();

        const float* Ab = &As[i & 3][0];
        const float* Wb = &Ws[i & 3][0];
        #pragma unroll
        for (int ks = 0; ks < 16; ks += 8) {
            unsigned af[2][4], bf[4][2];
            #pragma unroll
            for (int mm = 0; mm < 2; mm++) {
                const float* p = &Ab[(warp_m + mm * 16 + gid) * LDK + ks + tig];
                af[mm][0] = f2tf(p[0]);
                af[mm][1] = f2tf(p[8 * LDK]);
                af[mm][2] = f2tf(p[4]);
                af[mm][3] = f2tf(p[8 * LDK + 4]);
            }
            #pragma unroll
            for (int nn = 0; nn < 4; nn++) {
                const float* p = &Wb[(warp_n + nn * 8 + gid) * LDK + ks + tig];
                bf[nn][0] = f2tf(p[0]);
                bf[nn][1] = f2tf(p[4]);
            }
            #pragma unroll
            for (int mm = 0; mm < 2; mm++)
                #pragma unroll
                for (int nn = 0; nn < 4; nn++)
                    mma_tf32(acc[mm][nn], af[mm], bf[nn]);
        }
    }

    #pragma unroll
    for (int mm = 0; mm < 2; mm++) {
        int r0 = rb + warp_m + mm * 16 + gid;
        #pragma unroll
        for (int nn = 0; nn < 4; nn++) {
            int c = nb + warp_n + nn * 8 + 2 * tig;
            float2 v0 = make_float2(acc[mm][nn][0], acc[mm][nn][1]);
            float2 v1 = make_float2(acc[mm][nn][2], acc[mm][nn][3]);
            if (bias) {
                float2 bb = *(const float2*)&bias[c];
                v0.x += bb.x; v0.y += bb.y;
                v1.x += bb.x; v1.y += bb.y;
            }
            *(float2*)&C[(size_t)r0 * DIM_M + c]       = v0;
            *(float2*)&C[(size_t)(r0 + 8) * DIM_M + c] = v1;
        }
    }
}

// ---------------------------------------------------------------------------
// Scores: sc[b][q][l] = sum_m w[m] * tanh(kx[b][l][m] + qh[b][q][m])
// (unchanged: MUFU-bound, ~90% of floor)
// ---------------------------------------------------------------------------
__global__ __launch_bounds__(256) void score_kernel(const float* __restrict__ w)
{
    __shared__ float kxs[128][34];
    __shared__ float qhs[128][34];
    __shared__ float w_s[DIM_M];

    int tid = threadIdx.x;
    int tx = tid & 15, ty = tid >> 4;
    int lb = blockIdx.x * 32;
    int qb = blockIdx.y * 32;
    int b  = blockIdx.z;

    if (tid < DIM_M) w_s[tid] = w[tid];

    const float* kxp = g_kx + (b * LEN  + lb) * DIM_M;
    const float* qhp = g_qh + (b * LEN1 + qb) * DIM_M;

    float acc00 = 0.f, acc01 = 0.f, acc10 = 0.f, acc11 = 0.f;

    int mloc  = tid & 127;
    int lhalf = tid >> 7;

    for (int h = 0; h < 2; h++) {
        __syncthreads();
        int mg = h * 128 + mloc;
        #pragma unroll
        for (int i = 0; i < 16; i++) {
            int row = lhalf * 16 + i;
            kxs[mloc][row] = kxp[row * DIM_M + mg];
            qhs[mloc][row] = qhp[row * DIM_M + mg];
        }
        __syncthreads();

        #pragma unroll 8
        for (int mm = 0; mm < 128; mm++) {
            float  wm = w_s[h * 128 + mm];
            float2 qa = *(const float2*)&qhs[mm][ty * 2];
            float2 kb = *(const float2*)&kxs[mm][tx * 2];
            acc00 += wm * tanh_fast(qa.x + kb.x);
            acc01 += wm * tanh_fast(qa.x + kb.y);
            acc10 += wm * tanh_fast(qa.y + kb.x);
            acc11 += wm * tanh_fast(qa.y + kb.y);
        }
    }

    float* o = g_sc + (size_t)(b * LEN1 + qb + ty * 2) * LEN + lb + tx * 2;
    o[0]       = acc00; o[1]       = acc01;
    o[LEN]     = acc10; o[LEN + 1] = acc11;
}

// ---------------------------------------------------------------------------
// Softmax over last dim (512) of g_sc. One warp per row, shfl reductions.
// ---------------------------------------------------------------------------
__global__ __launch_bounds__(256) void softmax_kernel()
{
    int row  = blockIdx.x * 8 + (threadIdx.x >> 5);
    int lane = threadIdx.x & 31;
    float* p = g_sc + (size_t)row * LEN;

    float4 v[4];
    float mx = -1e30f;
    #pragma unroll
    for (int j = 0; j < 4; j++) {
        v[j] = *(float4*)&p[(lane + j * 32) * 4];
        mx = fmaxf(mx, fmaxf(fmaxf(v[j].x, v[j].y), fmaxf(v[j].z, v[j].w)));
    }
    #pragma unroll
    for (int s = 16; s > 0; s >>= 1)
        mx = fmaxf(mx, __shfl_xor_sync(0xFFFFFFFFu, mx, s));

    float sum = 0.f;
    #pragma unroll
    for (int j = 0; j < 4; j++) {
        v[j].x = __expf(v[j].x - mx); v[j].y = __expf(v[j].y - mx);
        v[j].z = __expf(v[j].z - mx); v[j].w = __expf(v[j].w - mx);
        sum += (v[j].x + v[j].y) + (v[j].z + v[j].w);
    }
    #pragma unroll
    for (int s = 16; s > 0; s >>= 1)
        sum += __shfl_xor_sync(0xFFFFFFFFu, sum, s);
    float inv = 1.0f / sum;

    #pragma unroll
    for (int j = 0; j < 4; j++) {
        v[j].x *= inv; v[j].y *= inv; v[j].z *= inv; v[j].w *= inv;
        *(float4*)&p[(lane + j * 32) * 4] = v[j];
    }
}

// ---------------------------------------------------------------------------
// av (NN, tensor core, 4-stage cp.async):
// out[b][q][v] = sum_l e[b][q][l] * values[b][l][v]. Batched 512^3.
// Block tile 64(q)x64(v), 128 threads, 4 warps. Grid = 8*8*4 = 256.
// ---------------------------------------------------------------------------
__global__ __launch_bounds__(128) void av_tc(
    const float* __restrict__ values, float* __restrict__ out)
{
    int bz = blockIdx.z;
    const float* E = g_sc   + (size_t)bz * LEN1 * LEN;
    const float* V = values + (size_t)bz * LEN * DIM_V;
    float*       C = out    + (size_t)bz * LEN1 * DIM_V;

    __shared__ __align__(16) float Es[4][64 * LDK];
    __shared__ __align__(16) float Vs[4][16 * LDN];

    int tid  = threadIdx.x;
    int lane = tid & 31;
    int wid  = tid >> 5;
    int warp_m = (wid & 1) * 32;
    int warp_n = (wid >> 1) * 32;
    int gid = lane >> 2;
    int tig = lane & 3;

    int rb = blockIdx.y * 64;   // q
    int nb = blockIdx.x * 64;   // v

    // cp.async mapping: E tile 64 q x 16 l -> (row=tid>>1, ku=(tid&1)*8)
    //                   V tile 16 l x 64 v -> (vrow=tid>>3, vu=(tid&7)*8)
    int erow = tid >> 1;
    int eku  = (tid & 1) * 8;
    int vrow = tid >> 3;
    int vu   = (tid & 7) * 8;
    const float* Egp = E + (size_t)(rb + erow) * LEN + eku;
    const float* Vgp = V + (size_t)vrow * DIM_V + nb + vu;
    uint32_t sE = (uint32_t)__cvta_generic_to_shared(&Es[0][0]) + (erow * LDK + eku) * 4;
    uint32_t sV = (uint32_t)__cvta_generic_to_shared(&Vs[0][0]) + (vrow * LDN + vu) * 4;
    const uint32_t stageE = 64 * LDK * 4;
    const uint32_t stageV = 16 * LDN * 4;

    float acc[2][4][4] = {};

    #pragma unroll
    for (int s = 0; s < 3; s++) {
        cp16(sE + s * stageE,      Egp + s * 16);
        cp16(sE + s * stageE + 16, Egp + s * 16 + 4);
        cp16(sV + s * stageV,      Vgp + (size_t)s * 16 * DIM_V);
        cp16(sV + s * stageV + 16, Vgp + (size_t)s * 16 * DIM_V + 4);
        CP_COMMIT();
    }

    for (int i = 0; i < 32; i++) {
        CP_WAIT2();
        __syncthreads();
        int ls = i + 3;
        if (ls < 32) {
            uint32_t offE = (uint32_t)(ls & 3) * stageE;
            uint32_t offV = (uint32_t)(ls & 3) * stageV;
            cp16(sE + offE,      Egp + ls * 16);
            cp16(sE + offE + 16, Egp + ls * 16 + 4);
            cp16(sV + offV,      Vgp + (size_t)ls * 16 * DIM_V);
            cp16(sV + offV + 16, Vgp + (size_t)ls * 16 * DIM_V + 4);
        }
        CP_COMMIT();

        const float* Eb = &Es[i & 3][0];
        const float* Vb = &Vs[i & 3][0];
        #pragma unroll
        for (int ks = 0; ks < 16; ks += 8) {
            unsigned af[2][4], bf[4][2];
            #pragma unroll
            for (int mm = 0; mm < 2; mm++) {
                const float* p = &Eb[(warp_m + mm * 16 + gid) * LDK + ks + tig];
                af[mm][0] = f2tf(p[0]);
                af[mm][1] = f2tf(p[8 * LDK]);
                af[mm][2] = f2tf(p[4]);
                af[mm][3] = f2tf(p[8 * LDK + 4]);
            }
            #pragma unroll
            for (int nn = 0; nn < 4; nn++) {
                const float* p = &Vb[(ks + tig) * LDN + warp_n + nn * 8 + gid];
                bf[nn][0] = f2tf(p[0]);
                bf[nn][1] = f2tf(p[4 * LDN]);
            }
            #pragma unroll
            for (int mm = 0; mm < 2; mm++)
                #pragma unroll
                for (int nn = 0; nn < 4; nn++)
                    mma_tf32(acc[mm][nn], af[mm], bf[nn]);
        }
    }

    #pragma unroll
    for (int mm = 0; mm < 2; mm++) {
        int r0 = rb + warp_m + mm * 16 + gid;
        #pragma unroll
        for (int nn = 0; nn < 4; nn++) {
            int c = nb + warp_n + nn * 8 + 2 * tig;
            *(float2*)&C[(size_t)r0 * DIM_V + c] =
                make_float2(acc[mm][nn][0], acc[mm][nn][1]);
            *(float2*)&C[(size_t)(r0 + 8) * DIM_V + c] =
                make_float2(acc[mm][nn][2], acc[mm][nn][3]);
        }
    }
}

// ---------------------------------------------------------------------------
// Launch. Inputs: query, keys, values, Wx, Wh, bh, w. Output [B, LEN1, DIM_V].
// ---------------------------------------------------------------------------
extern "C" void kernel_launch(void* const* d_in, const int* in_sizes, int n_in,
                              void* d_out, int out_size)
{
    const float* query  = (const float*)d_in[0];
    const float* keys   = (const float*)d_in[1];
    const float* values = (const float*)d_in[2];
    const float* Wx     = (const float*)d_in[3];
    const float* Wh     = (const float*)d_in[4];
    const float* bh     = (const float*)d_in[5];
    const float* w      = (const float*)d_in[6];
    float* out = (float*)d_out;

    proj_tc<<<dim3(DIM_M / 64, (BB * LEN) / 64, 2), 128>>>(keys, query, Wx, Wh, bh);
    score_kernel<<<dim3(LEN / 32, LEN1 / 32, BB), 256>>>(w);
    softmax_kernel<<<(BB * LEN1) / 8, 256>>>();
    av_tc<<<dim3(DIM_V / 64, LEN1 / 64, BB), 128>>>(values, out);
}